// round 17
// baseline (speedup 1.0000x reference)
#include <cuda_runtime.h>
#include <cstdint>

// out[n,d] = mean_f( x[n,f]*W[f,d] + b[f,d] ) = (x@W)[n,d]/256 + mean_f b[f,d]
// N=8192, K=256, D=64. Single kernel. bf16 3-term split, mma.sync m16n8k16.
// TILE_M=64, 512 threads, grid=128: 1 CTA/SM, W/b conversion amortized 2x,
// per-SM L1 traffic halved vs TILE_M=32 champion. Mainloop unchanged.

typedef uint32_t u32;

#define NROWS  8192
#define NF     256
#define ND     64
#define TILE_M 64
#define THREADS 512
#define NBLOCKS (NROWS / TILE_M)   // 128

// padded bf16 pitches (bytes): conflict-free ldmatrix
#define XPITCHB (264 * 2)   // 528
#define WPITCHB (72 * 2)    // 144

#define XH_OFF 0
#define XL_OFF (XH_OFF + TILE_M * XPITCHB)   // 33792
#define WH_OFF (XL_OFF + TILE_M * XPITCHB)   // 67584
#define WL_OFF (WH_OFF + NF * WPITCHB)       // 104448
#define MB_OFF (WL_OFF + NF * WPITCHB)       // 141312
#define SC_OFF (MB_OFF + 256)                // 141568 (512 float4 scratch)
#define SMEM_BYTES (SC_OFF + 8192)           // 149760

__device__ __forceinline__ u32 smem_u32(const void* p) {
    u32 a;
    asm("{ .reg .u64 t; cvta.to.shared.u64 t, %1; cvt.u32.u64 %0, t; }" : "=r"(a) : "l"(p));
    return a;
}
__device__ __forceinline__ void cvt_split(float a, float b, u32& hi, u32& lo) {
    asm("cvt.rn.bf16x2.f32 %0, %1, %2;" : "=r"(hi) : "f"(b), "f"(a));
    float ha = __uint_as_float(hi << 16);
    float hb = __uint_as_float(hi & 0xFFFF0000u);
    float ra = a - ha;
    float rb = b - hb;
    asm("cvt.rn.bf16x2.f32 %0, %1, %2;" : "=r"(lo) : "f"(rb), "f"(ra));
}
__device__ __forceinline__ void ldsm4(u32* r, u32 addr) {
    asm volatile("ldmatrix.sync.aligned.m8n8.x4.shared.b16 {%0,%1,%2,%3}, [%4];"
        : "=r"(r[0]), "=r"(r[1]), "=r"(r[2]), "=r"(r[3]) : "r"(addr));
}
__device__ __forceinline__ void ldsm4t(u32* r, u32 addr) {
    asm volatile("ldmatrix.sync.aligned.m8n8.x4.trans.shared.b16 {%0,%1,%2,%3}, [%4];"
        : "=r"(r[0]), "=r"(r[1]), "=r"(r[2]), "=r"(r[3]) : "r"(addr));
}
__device__ __forceinline__ void mma16816(float* c, const u32* a, u32 b0, u32 b1) {
    asm volatile(
        "mma.sync.aligned.m16n8k16.row.col.f32.bf16.bf16.f32 "
        "{%0,%1,%2,%3}, {%4,%5,%6,%7}, {%8,%9}, {%0,%1,%2,%3};"
        : "+f"(c[0]), "+f"(c[1]), "+f"(c[2]), "+f"(c[3])
        : "r"(a[0]), "r"(a[1]), "r"(a[2]), "r"(a[3]), "r"(b0), "r"(b1));
}

__global__ void __launch_bounds__(THREADS, 1)
nanembed_hmma_kernel(const float* __restrict__ x,
                     const float* __restrict__ W,
                     const float* __restrict__ b,
                     float* __restrict__ out)
{
    extern __shared__ char smem[];
    const u32 sb = smem_u32(smem);
    const int tid = threadIdx.x;

    // ---- 1) issue x tile loads (DRAM, 8 float4/thread = 64 rows x 256) ----
    const float4* x4 = (const float4*)(x + (size_t)blockIdx.x * TILE_M * NF);
    float4 xv[8];
    #pragma unroll
    for (int i = 0; i < 8; ++i)
        xv[i] = x4[tid + THREADS * i];

    // ---- 2) issue ALL W loads (L2, 8 float4/thread = whole 256x64 W) ----
    const float4* W4 = (const float4*)W;
    float4 wv[8];
    #pragma unroll
    for (int i = 0; i < 8; ++i)
        wv[i] = W4[tid + THREADS * i];

    // ---- 3) convert x -> XH/XL (x DRAM stall absorbed; W in flight) ----
    #pragma unroll
    for (int i = 0; i < 8; ++i) {
        int idx = tid + THREADS * i;          // 0..4095
        int row = idx >> 6;                   // 0..63
        int c4  = idx & 63;
        u32 h0, l0, h1, l1;
        cvt_split(xv[i].x, xv[i].y, h0, l0);
        cvt_split(xv[i].z, xv[i].w, h1, l1);
        u32 off = (u32)(row * XPITCHB + c4 * 8);
        asm volatile("st.shared.v2.b32 [%0], {%1, %2};"
                     :: "r"(sb + XH_OFF + off), "r"(h0), "r"(h1) : "memory");
        asm volatile("st.shared.v2.b32 [%0], {%1, %2};"
                     :: "r"(sb + XL_OFF + off), "r"(l0), "r"(l1) : "memory");
    }

    // ---- 4) issue b loads (L2), then convert W ----
    const int qd = tid & 15;                  // d-quad
    const int fr = tid >> 4;                  // f-group 0..31 (8 rows each)
    const float4* b4 = (const float4*)b;      // [256][16] float4
    float4 bv[8];
    #pragma unroll
    for (int k = 0; k < 8; ++k)
        bv[k] = b4[(fr * 8 + k) * 16 + qd];

    #pragma unroll
    for (int i = 0; i < 8; ++i) {
        int idx = tid + THREADS * i;          // 0..4095
        int row = idx >> 4;                   // 0..255 (16 float4 per W row)
        int c4  = idx & 15;
        u32 h0, l0, h1, l1;
        cvt_split(wv[i].x, wv[i].y, h0, l0);
        cvt_split(wv[i].z, wv[i].w, h1, l1);
        u32 off = (u32)(row * WPITCHB + c4 * 8);
        asm volatile("st.shared.v2.b32 [%0], {%1, %2};"
                     :: "r"(sb + WH_OFF + off), "r"(h0), "r"(h1) : "memory");
        asm volatile("st.shared.v2.b32 [%0], {%1, %2};"
                     :: "r"(sb + WL_OFF + off), "r"(l0), "r"(l1) : "memory");
    }

    // ---- 5) b partial sums -> scratch ----
    {
        float4 s = make_float4(0.f, 0.f, 0.f, 0.f);
        #pragma unroll
        for (int k = 0; k < 8; ++k) {
            s.x += bv[k].x; s.y += bv[k].y; s.z += bv[k].z; s.w += bv[k].w;
        }
        ((float4*)(smem + SC_OFF))[tid] = s;
    }
    __syncthreads();
    if (tid < 16) {
        float4* sc = (float4*)(smem + SC_OFF);
        float4 m = make_float4(0.f, 0.f, 0.f, 0.f);
        #pragma unroll
        for (int g = 0; g < 32; ++g) {
            float4 v = sc[tid + 16 * g];
            m.x += v.x; m.y += v.y; m.z += v.z; m.w += v.w;
        }
        const float inv = 1.f / 256.f;
        m.x *= inv; m.y *= inv; m.z *= inv; m.w *= inv;
        ((float4*)(smem + MB_OFF))[tid] = m;
    }
    __syncthreads();

    // ---- mainloop: 16 warps = 4 row-groups x 4 col-groups, 16x16 each ----
    const int wid  = tid >> 5;
    const int lane = tid & 31;
    const int r0   = (wid & 3) * 16;
    const int n0   = (wid >> 2) * 16;
    const int g    = lane >> 2;
    const int t4   = lane & 3;

    const u32 aRow = (u32)(r0 + (lane & 15));
    const u32 aCol = (u32)((lane >> 4) * 16);
    u32 aAddrH = sb + XH_OFF + aRow * XPITCHB + aCol;
    u32 aAddrL = aAddrH + (u32)(XL_OFF - XH_OFF);
    const u32 bRow = (u32)(lane & 15);
    const u32 bCol = (u32)(n0 * 2 + (lane >> 4) * 16);
    u32 bAddrH = sb + WH_OFF + bRow * WPITCHB + bCol;
    u32 bAddrL = bAddrH + (u32)(WL_OFF - WH_OFF);

    float a0hh[4]={0,0,0,0}, a0hl[4]={0,0,0,0}, a0lh[4]={0,0,0,0};
    float a1hh[4]={0,0,0,0}, a1hl[4]={0,0,0,0}, a1lh[4]={0,0,0,0};

    u32 ah[2][4], al[2][4], bh[2][4], bl[2][4];
    ldsm4 (ah[0], aAddrH);
    ldsm4 (al[0], aAddrL);
    ldsm4t(bh[0], bAddrH);
    ldsm4t(bl[0], bAddrL);

    #pragma unroll
    for (int ki = 0; ki < 16; ++ki) {
        const int cur = ki & 1;
        const int nxt = cur ^ 1;
        if (ki < 15) {
            ldsm4 (ah[nxt], aAddrH + (u32)(ki + 1) * 32);
            ldsm4 (al[nxt], aAddrL + (u32)(ki + 1) * 32);
            ldsm4t(bh[nxt], bAddrH + (u32)(ki + 1) * (16 * WPITCHB));
            ldsm4t(bl[nxt], bAddrL + (u32)(ki + 1) * (16 * WPITCHB));
        }
        mma16816(a0hh, ah[cur], bh[cur][0], bh[cur][1]);
        mma16816(a1hh, ah[cur], bh[cur][2], bh[cur][3]);
        mma16816(a0hl, ah[cur], bl[cur][0], bl[cur][1]);
        mma16816(a1hl, ah[cur], bl[cur][2], bl[cur][3]);
        mma16816(a0lh, al[cur], bh[cur][0], bh[cur][1]);
        mma16816(a1lh, al[cur], bh[cur][2], bh[cur][3]);
    }

    // ---- epilogue: combine terms, scale, add bias-mean ----
    const float* mb = (const float*)(smem + MB_OFF);
    const float inv = 1.f / 256.f;
    const int grow = blockIdx.x * TILE_M + r0 + g;
    {
        int col = n0 + 2 * t4;
        float2 m = *(const float2*)(mb + col);
        float s0 = a0hh[0] + a0hl[0] + a0lh[0];
        float s1 = a0hh[1] + a0hl[1] + a0lh[1];
        float s2 = a0hh[2] + a0hl[2] + a0lh[2];
        float s3 = a0hh[3] + a0hl[3] + a0lh[3];
        float2 o0, o1;
        o0.x = fmaf(s0, inv, m.x); o0.y = fmaf(s1, inv, m.y);
        o1.x = fmaf(s2, inv, m.x); o1.y = fmaf(s3, inv, m.y);
        *(float2*)(out + (size_t)grow * ND + col) = o0;
        *(float2*)(out + (size_t)(grow + 8) * ND + col) = o1;
    }
    {
        int col = n0 + 8 + 2 * t4;
        float2 m = *(const float2*)(mb + col);
        float s0 = a1hh[0] + a1hl[0] + a1lh[0];
        float s1 = a1hh[1] + a1hl[1] + a1lh[1];
        float s2 = a1hh[2] + a1hl[2] + a1lh[2];
        float s3 = a1hh[3] + a1hl[3] + a1lh[3];
        float2 o0, o1;
        o0.x = fmaf(s0, inv, m.x); o0.y = fmaf(s1, inv, m.y);
        o1.x = fmaf(s2, inv, m.x); o1.y = fmaf(s3, inv, m.y);
        *(float2*)(out + (size_t)grow * ND + col) = o0;
        *(float2*)(out + (size_t)(grow + 8) * ND + col) = o1;
    }
}

extern "C" void kernel_launch(void* const* d_in, const int* in_sizes, int n_in,
                              void* d_out, int out_size)
{
    const float* x = (const float*)d_in[0];
    const float* W = (const float*)d_in[1];
    const float* b = (const float*)d_in[2];
    float* out = (float*)d_out;

    cudaFuncSetAttribute(nanembed_hmma_kernel,
                         cudaFuncAttributeMaxDynamicSharedMemorySize, SMEM_BYTES);
    nanembed_hmma_kernel<<<NBLOCKS, THREADS, SMEM_BYTES>>>(x, W, b, out);
}